// round 2
// baseline (speedup 1.0000x reference)
#include <cuda_runtime.h>
#include <stdint.h>

#define Nn   4096
#define Dd   512
#define NE   131072
#define WPR  128      // 4096 bits / 32 per row
#define SLOTS 128     // max nnz slots per row (Poisson(32), >20 sigma safe)
#define KITERS 20

// ---------------- scratch (no allocations allowed) ----------------
__device__ uint32_t g_bitmap[Nn * WPR];      // 2 MB dedupe bitmap
__device__ int      g_cols[Nn * SLOTS];      // fixed-stride CSR cols
__device__ int      g_cnt[Nn];               // nnz per row
__device__ float    g_dinv[Nn];              // 1/sqrt(deg)
__device__ float    g_R[Nn * Dd];            // R = (I + 0.5*Ahat) X
__device__ float    g_A[Nn * Dd];            // ping
__device__ float    g_B[Nn * Dd];            // pong
__device__ int      g_is64;                  // 1 if edge_index is int64

// ---------------- setup kernels ----------------
__global__ void k_zero_bitmap() {
    int i = blockIdx.x * blockDim.x + threadIdx.x;   // 131072 uint4 = 2MB
    ((uint4*)g_bitmap)[i] = make_uint4(0u, 0u, 0u, 0u);
}

// Detect int64 vs int32 edge layout: for little-endian int64 values in
// [0,4096), every odd 32-bit word is 0. For int32 data, 1024 random odd
// words being all-zero has probability (1/4096)^1024 ~ 0.
__global__ void k_sniff(const int* __restrict__ ei32) {
    if (threadIdx.x == 0 && blockIdx.x == 0) {
        int acc = 0;
        for (int k = 1; k < 2048; k += 2) acc |= ei32[k];
        g_is64 = (acc == 0) ? 1 : 0;
    }
}

__global__ void k_scatter(const int* __restrict__ ei32) {
    int e = blockIdx.x * blockDim.x + threadIdx.x;
    if (e < NE) {
        int s, d;
        if (g_is64) {
            s = ei32[2 * e];            // low word of int64 src
            d = ei32[2 * (NE + e)];     // low word of int64 dst
        } else {
            s = ei32[e];
            d = ei32[NE + e];
        }
        atomicOr(&g_bitmap[s * WPR + (d >> 5)], 1u << (d & 31));
    }
}

// one warp per row: popcount -> warp scan -> ordered compaction
__global__ void k_build() {
    int warp = (blockIdx.x * blockDim.x + threadIdx.x) >> 5;
    int lane = threadIdx.x & 31;
    if (warp >= Nn) return;
    const uint32_t* rowbm = &g_bitmap[warp * WPR];
    uint32_t w[4];
    int c = 0;
#pragma unroll
    for (int k = 0; k < 4; k++) { w[k] = rowbm[lane * 4 + k]; c += __popc(w[k]); }
    int incl = c;
#pragma unroll
    for (int d = 1; d < 32; d <<= 1) {
        int v = __shfl_up_sync(0xFFFFFFFFu, incl, d);
        if (lane >= d) incl += v;
    }
    int total = __shfl_sync(0xFFFFFFFFu, incl, 31);
    int off = incl - c;  // exclusive
    int* dst = &g_cols[warp * SLOTS];
#pragma unroll
    for (int k = 0; k < 4; k++) {
        uint32_t m = w[k];
        int base = (lane * 4 + k) << 5;
        while (m) {
            int b = __ffs(m) - 1;
            m &= m - 1;
            dst[off++] = base + b;
        }
    }
    if (lane == 0) {
        g_cnt[warp]  = total;
        g_dinv[warp] = rsqrtf((float)(total + 1));  // +1 for the added I
    }
}

// ---------------- fused SpMM + axpy ----------------
// out[i,c] = a*base[i,c] + b * dinv_i * ( sum_{j in row i} dinv_j * in[j,c]  +  dinv_i * in[i,c] )
__global__ __launch_bounds__(512) void k_matvec(
    const float* __restrict__ in, const float* __restrict__ base,
    float* __restrict__ out, float a, float b)
{
    int row = blockIdx.x;
    int col = threadIdx.x;            // blockDim.x == 512 == Dd
    int cnt = g_cnt[row];
    float di = g_dinv[row];
    const int* cols = &g_cols[row * SLOTS];
    long idx = (long)row * Dd + col;

    float s = di * __ldg(&in[idx]);   // +I self term
    int k = 0;
    for (; k + 4 <= cnt; k += 4) {
        int j0 = __ldg(&cols[k]),     j1 = __ldg(&cols[k + 1]);
        int j2 = __ldg(&cols[k + 2]), j3 = __ldg(&cols[k + 3]);
        float w0 = __ldg(&g_dinv[j0]), w1 = __ldg(&g_dinv[j1]);
        float w2 = __ldg(&g_dinv[j2]), w3 = __ldg(&g_dinv[j3]);
        float v0 = __ldg(&in[(long)j0 * Dd + col]);
        float v1 = __ldg(&in[(long)j1 * Dd + col]);
        float v2 = __ldg(&in[(long)j2 * Dd + col]);
        float v3 = __ldg(&in[(long)j3 * Dd + col]);
        s += w0 * v0 + w1 * v1 + w2 * v2 + w3 * v3;
    }
    for (; k < cnt; k++) {
        int j = __ldg(&cols[k]);
        s += __ldg(&g_dinv[j]) * __ldg(&in[(long)j * Dd + col]);
    }
    out[idx] = a * __ldg(&base[idx]) + b * di * s;
}

// ---------------- launch ----------------
extern "C" void kernel_launch(void* const* d_in, const int* in_sizes, int n_in,
                              void* d_out, int out_size) {
    // Bind inputs by element count: x has 4096*512 = 2097152, edges 262144.
    const float* x    = (const float*)d_in[0];
    const void*  eraw = d_in[1];
    if (in_sizes[0] != Nn * Dd) {       // order flipped
        x    = (const float*)d_in[1];
        eraw = d_in[0];
    }
    const int* ei32 = (const int*)eraw;
    float*     yo   = (float*)d_out;

    float *pR, *pA, *pB;
    cudaGetSymbolAddress((void**)&pR, g_R);
    cudaGetSymbolAddress((void**)&pA, g_A);
    cudaGetSymbolAddress((void**)&pB, g_B);

    // build normalized adjacency structure (dedup via bitmap)
    k_zero_bitmap<<<512, 256>>>();
    k_sniff<<<1, 32>>>(ei32);
    k_scatter<<<NE / 256, 256>>>(ei32);
    k_build<<<Nn / 8, 256>>>();          // 8 warps/block, warp per row

    // R = X + 0.5 * Ahat * X
    k_matvec<<<Nn, 512>>>(x, x, pR, 1.0f, 0.5f);

    // Horner Neumann: acc <- R + 0.6 * Ahat * acc ; final Y = 0.4 * acc
    const float* in = pR;
    float* bufs[2] = { pA, pB };
    for (int i = 0; i < KITERS; i++) {
        bool last = (i == KITERS - 1);
        float* o = last ? yo : bufs[i & 1];
        float a  = last ? 0.4f : 1.0f;
        float b  = last ? 0.4f * 0.6f : 0.6f;
        k_matvec<<<Nn, 512>>>(in, pR, o, a, b);
        in = o;
    }
}

// round 3
// speedup vs baseline: 4.0814x; 4.0814x over previous
#include <cuda_runtime.h>
#include <stdint.h>

#define Nn    4096
#define Dd    512
#define D4    128        // Dd/4
#define NE    131072
#define WPR   128        // 4096 bits / 32 per row
#define SLOTS 128
#define NPOW  10         // power iterations (must be even: ends in g_u)
#define KBULK 6          // deflated Neumann passes

// ---------------- scratch ----------------
__device__ uint32_t g_bm [Nn * WPR];     // forward bitmap (2MB)
__device__ uint32_t g_bmT[Nn * WPR];     // transpose bitmap (2MB)
__device__ int      g_cols [Nn * SLOTS];
__device__ int      g_colsT[Nn * SLOTS];
__device__ int      g_cnt [Nn];
__device__ int      g_cntT[Nn];
__device__ float    g_dinv[Nn];          // 1/sqrt(deg)
__device__ float    g_v[Nn];             // sqrt(deg) = right Perron eigvec
__device__ float    g_u[Nn], g_u2[Nn];   // left Perron eigvec (power iter)
__device__ float    g_q[Dd];             // u^T R / (u^T v)
__device__ float    g_qscale;            // 1/(u^T v)
__device__ float    g_R[Nn * Dd];        // R, then acc ping
__device__ float    g_A[Nn * Dd];        // R' (deflated base)
__device__ float    g_B[Nn * Dd];        // acc pong
__device__ int      g_is64;

// ---------------- setup ----------------
__global__ void k_zero_bitmaps() {          // 4MB total
    int i = blockIdx.x * blockDim.x + threadIdx.x;   // 262144 uint4
    if (i < Nn * WPR / 4)      ((uint4*)g_bm )[i]              = make_uint4(0,0,0,0);
    else                       ((uint4*)g_bmT)[i - Nn*WPR/4]   = make_uint4(0,0,0,0);
}

__global__ void k_sniff(const int* __restrict__ ei32) {
    if (threadIdx.x == 0 && blockIdx.x == 0) {
        int acc = 0;
        for (int k = 1; k < 2048; k += 2) acc |= ei32[k];
        g_is64 = (acc == 0) ? 1 : 0;
    }
}

__global__ void k_scatter2(const int* __restrict__ ei32) {
    int e = blockIdx.x * blockDim.x + threadIdx.x;
    if (e < NE) {
        int s, d;
        if (g_is64) { s = ei32[2*e]; d = ei32[2*(NE+e)]; }
        else        { s = ei32[e];   d = ei32[NE+e]; }
        atomicOr(&g_bm [s * WPR + (d >> 5)], 1u << (d & 31));
        atomicOr(&g_bmT[d * WPR + (s >> 5)], 1u << (s & 31));
    }
}

// warp per row: popcount -> scan -> ordered compaction
__global__ void k_build(const uint32_t* __restrict__ bm, int* __restrict__ colsOut,
                        int* __restrict__ cntOut, int writeStats) {
    int warp = (blockIdx.x * blockDim.x + threadIdx.x) >> 5;
    int lane = threadIdx.x & 31;
    if (warp >= Nn) return;
    const uint32_t* rowbm = &bm[warp * WPR];
    uint32_t w[4]; int c = 0;
#pragma unroll
    for (int k = 0; k < 4; k++) { w[k] = rowbm[lane*4 + k]; c += __popc(w[k]); }
    int incl = c;
#pragma unroll
    for (int d = 1; d < 32; d <<= 1) {
        int t = __shfl_up_sync(0xFFFFFFFFu, incl, d);
        if (lane >= d) incl += t;
    }
    int total = __shfl_sync(0xFFFFFFFFu, incl, 31);
    int off = incl - c;
    int* dst = &colsOut[warp * SLOTS];
#pragma unroll
    for (int k = 0; k < 4; k++) {
        uint32_t m = w[k];
        int base = (lane*4 + k) << 5;
        while (m) { int b = __ffs(m) - 1; m &= m - 1; dst[off++] = base + b; }
    }
    if (lane == 0) {
        cntOut[warp] = total;
        if (writeStats) {
            float deg = (float)(total + 1);
            g_dinv[warp] = rsqrtf(deg);
            g_v[warp]    = sqrtf(deg);
        }
    }
}

// ---------------- left Perron eigenvector ----------------
__global__ void k_uinit() {
    int i = blockIdx.x * blockDim.x + threadIdx.x;
    if (i < Nn) g_u[i] = 1.0f;
}

// uout = Ahat^T uin  (no normalization: lambda=1, bulk decays)
__global__ void k_power(const float* __restrict__ uin, float* __restrict__ uout) {
    int warp = (blockIdx.x * blockDim.x + threadIdx.x) >> 5;
    int lane = threadIdx.x & 31;
    if (warp >= Nn) return;
    int cnt = g_cntT[warp];
    const int* cols = &g_colsT[warp * SLOTS];
    float s = 0.f;
    for (int k = lane; k < cnt; k += 32) {
        int j = cols[k];
        s += g_dinv[j] * uin[j];
    }
#pragma unroll
    for (int d = 16; d; d >>= 1) s += __shfl_down_sync(0xFFFFFFFFu, s, d);
    if (lane == 0) {
        float di = g_dinv[warp];
        uout[warp] = di * (s + di * uin[warp]);
    }
}

__global__ void k_dot() {   // g_qscale = 1/(u^T v)
    __shared__ float sh[32];
    int t = threadIdx.x;
    float s = 0.f;
    for (int i = t; i < Nn; i += 1024) s += g_u[i] * g_v[i];
#pragma unroll
    for (int d = 16; d; d >>= 1) s += __shfl_down_sync(0xFFFFFFFFu, s, d);
    if ((t & 31) == 0) sh[t >> 5] = s;
    __syncthreads();
    if (t < 32) {
        s = sh[t];
#pragma unroll
        for (int d = 16; d; d >>= 1) s += __shfl_down_sync(0xFFFFFFFFu, s, d);
        if (t == 0) g_qscale = 1.0f / s;
    }
}

// ---------------- q = (u^T R) * qscale ----------------
__global__ void k_qzero() { g_q[threadIdx.x] = 0.f; }

__global__ void k_qaccum(const float* __restrict__ R) {
    int c = threadIdx.x;                 // 512 columns
    int r0 = blockIdx.x * 128;           // 32 blocks x 128 rows
    float s = 0.f;
    for (int k = 0; k < 128; k++)
        s += g_u[r0 + k] * R[(long)(r0 + k) * Dd + c];
    atomicAdd(&g_q[c], s);
}

__global__ void k_qfin() { g_q[threadIdx.x] *= g_qscale; }

// R'[i,c] = R[i,c] - v_i * q[c]
__global__ void k_r1(const float4* __restrict__ R, float4* __restrict__ Rp) {
    int i = blockIdx.x * blockDim.x + threadIdx.x;   // 524288 float4
    int row = i >> 7, c4 = i & 127;
    float vr = g_v[row];
    float4 q = ((const float4*)g_q)[c4];
    float4 x = R[i];
    x.x -= vr * q.x; x.y -= vr * q.y; x.z -= vr * q.z; x.w -= vr * q.w;
    Rp[i] = x;
}

// ---------------- fused SpMM + axpy + rank-1 ----------------
// out[i,c] = a*base[i,c] + b*dinv_i*(sum_j dinv_j*in[j,c] + dinv_i*in[i,c]) + r*v_i*q[c]
__global__ __launch_bounds__(128) void k_matvec(
    const float4* __restrict__ in, const float4* __restrict__ base,
    float4* __restrict__ out, float a, float b, float r)
{
    int row = blockIdx.x;
    int col = threadIdx.x;               // 128 float4 lanes = 512 cols
    int cnt = g_cnt[row];
    float di = g_dinv[row];
    const int* cols = &g_cols[row * SLOTS];
    long idx = (long)row * D4 + col;

    float4 sv = __ldg(&in[idx]);
    float4 s;
    s.x = di * sv.x; s.y = di * sv.y; s.z = di * sv.z; s.w = di * sv.w;

    int k = 0;
    for (; k + 4 <= cnt; k += 4) {
        int j0 = __ldg(&cols[k]),   j1 = __ldg(&cols[k+1]);
        int j2 = __ldg(&cols[k+2]), j3 = __ldg(&cols[k+3]);
        float w0 = __ldg(&g_dinv[j0]), w1 = __ldg(&g_dinv[j1]);
        float w2 = __ldg(&g_dinv[j2]), w3 = __ldg(&g_dinv[j3]);
        float4 v0 = __ldg(&in[(long)j0 * D4 + col]);
        float4 v1 = __ldg(&in[(long)j1 * D4 + col]);
        float4 v2 = __ldg(&in[(long)j2 * D4 + col]);
        float4 v3 = __ldg(&in[(long)j3 * D4 + col]);
        s.x += w0*v0.x + w1*v1.x + w2*v2.x + w3*v3.x;
        s.y += w0*v0.y + w1*v1.y + w2*v2.y + w3*v3.y;
        s.z += w0*v0.z + w1*v1.z + w2*v2.z + w3*v3.z;
        s.w += w0*v0.w + w1*v1.w + w2*v2.w + w3*v3.w;
    }
    for (; k < cnt; k++) {
        int j = __ldg(&cols[k]);
        float w = __ldg(&g_dinv[j]);
        float4 v = __ldg(&in[(long)j * D4 + col]);
        s.x += w*v.x; s.y += w*v.y; s.z += w*v.z; s.w += w*v.w;
    }
    float4 bs = __ldg(&base[idx]);
    float bd = b * di;
    float rv = r * g_v[row];
    float4 q = ((const float4*)g_q)[col];
    float4 o;
    o.x = a*bs.x + bd*s.x + rv*q.x;
    o.y = a*bs.y + bd*s.y + rv*q.y;
    o.z = a*bs.z + bd*s.z + rv*q.z;
    o.w = a*bs.w + bd*s.w + rv*q.w;
    out[idx] = o;
}

// ---------------- launch ----------------
extern "C" void kernel_launch(void* const* d_in, const int* in_sizes, int n_in,
                              void* d_out, int out_size) {
    const float* x    = (const float*)d_in[0];
    const void*  eraw = d_in[1];
    if (in_sizes[0] != Nn * Dd) { x = (const float*)d_in[1]; eraw = d_in[0]; }
    const int* ei32 = (const int*)eraw;
    float4*    yo   = (float4*)d_out;

    float *pR, *pA, *pB;
    cudaGetSymbolAddress((void**)&pR, g_R);
    cudaGetSymbolAddress((void**)&pA, g_A);
    cudaGetSymbolAddress((void**)&pB, g_B);
    float *pu, *pu2;
    cudaGetSymbolAddress((void**)&pu,  g_u);
    cudaGetSymbolAddress((void**)&pu2, g_u2);
    uint32_t *pbm, *pbmT;
    cudaGetSymbolAddress((void**)&pbm,  g_bm);
    cudaGetSymbolAddress((void**)&pbmT, g_bmT);
    int *pcols, *pcolsT, *pcnt, *pcntT;
    cudaGetSymbolAddress((void**)&pcols,  g_cols);
    cudaGetSymbolAddress((void**)&pcolsT, g_colsT);
    cudaGetSymbolAddress((void**)&pcnt,   g_cnt);
    cudaGetSymbolAddress((void**)&pcntT,  g_cntT);

    // adjacency structure (dedup) forward + transpose
    k_zero_bitmaps<<<2048, 256>>>();
    k_sniff<<<1, 32>>>(ei32);
    k_scatter2<<<NE / 256, 256>>>(ei32);
    k_build<<<Nn/8, 256>>>(pbm,  pcols,  pcnt,  1);
    k_build<<<Nn/8, 256>>>(pbmT, pcolsT, pcntT, 0);

    // left Perron eigenvector u (power iteration on Ahat^T)
    k_uinit<<<4, 1024>>>();
    for (int i = 0; i < NPOW / 2; i++) {
        k_power<<<128, 1024>>>(pu,  pu2);
        k_power<<<128, 1024>>>(pu2, pu);
    }
    k_dot<<<1, 1024>>>();

    // R = (I + 0.5*Ahat) X   (rank-1 term off; g_q stale but r=0)
    k_qzero<<<1, Dd>>>();
    k_matvec<<<Nn, 128>>>((const float4*)x, (const float4*)x, (float4*)pR,
                          1.0f, 0.5f, 0.0f);

    // q = u^T R / (u^T v);  R' = R - v q^T
    k_qaccum<<<32, Dd>>>(pR);
    k_qfin<<<1, Dd>>>();
    k_r1<<<2048, 256>>>((const float4*)pR, (float4*)pA);

    // deflated Neumann (bulk radius ~0.1/iter):
    // acc <- R' + 0.6*Ahat*acc;  Y = v q^T + 0.4*acc_final
    float4* bufs[2] = { (float4*)pB, (float4*)pR };
    const float4* in = (const float4*)pA;
    for (int i = 0; i < KBULK; i++) {
        bool last = (i == KBULK - 1);
        float4* o = last ? yo : bufs[i & 1];
        float a = last ? 0.4f  : 1.0f;
        float b = last ? 0.24f : 0.6f;
        float r = last ? 1.0f  : 0.0f;
        k_matvec<<<Nn, 128>>>(in, (const float4*)pA, o, a, b, r);
        in = o;
    }
}

// round 4
// speedup vs baseline: 5.2151x; 1.2778x over previous
#include <cuda_runtime.h>
#include <cuda_bf16.h>
#include <stdint.h>

#define Nn    4096
#define Dd    512
#define D4    128        // Dd/4 (float4 lanes)
#define NE    131072
#define WPR   128
#define SLOTS 128
#define NPOW  6          // power iterations (even)
#define KBULK 4          // deflated Neumann passes

// ---------------- scratch ----------------
__device__ uint32_t g_bm [Nn * WPR];
__device__ uint32_t g_bmT[Nn * WPR];
__device__ int      g_cols [Nn * SLOTS];
__device__ int      g_colsT[Nn * SLOTS];
__device__ int      g_cnt [Nn];
__device__ int      g_cntT[Nn];
__device__ float    g_dinv[Nn];
__device__ float    g_v[Nn];
__device__ float    g_u[Nn], g_u2[Nn];
__device__ float    g_q[Dd];
__device__ float    g_qscale;
__device__ float    g_R[Nn * Dd];        // R (fp32)
__device__ float    g_A[Nn * Dd];        // R' (fp32 base)
__device__ uint2    g_bf0[Nn * D4];      // bf16 iterate ping (4MB)
__device__ uint2    g_bf1[Nn * D4];      // bf16 iterate pong (4MB)
__device__ int      g_is64;

// ---------------- setup ----------------
__global__ void k_zero_bitmaps() {
    int i = blockIdx.x * blockDim.x + threadIdx.x;
    if (i < Nn * WPR / 4)  ((uint4*)g_bm )[i]             = make_uint4(0,0,0,0);
    else                   ((uint4*)g_bmT)[i - Nn*WPR/4]  = make_uint4(0,0,0,0);
}

__global__ void k_sniff(const int* __restrict__ ei32) {
    if (threadIdx.x == 0 && blockIdx.x == 0) {
        int acc = 0;
        for (int k = 1; k < 2048; k += 2) acc |= ei32[k];
        g_is64 = (acc == 0) ? 1 : 0;
    }
}

__global__ void k_scatter2(const int* __restrict__ ei32) {
    int e = blockIdx.x * blockDim.x + threadIdx.x;
    if (e < NE) {
        int s, d;
        if (g_is64) { s = ei32[2*e]; d = ei32[2*(NE+e)]; }
        else        { s = ei32[e];   d = ei32[NE+e]; }
        atomicOr(&g_bm [s * WPR + (d >> 5)], 1u << (d & 31));
        atomicOr(&g_bmT[d * WPR + (s >> 5)], 1u << (s & 31));
    }
}

__global__ void k_build(const uint32_t* __restrict__ bm, int* __restrict__ colsOut,
                        int* __restrict__ cntOut, int writeStats) {
    int warp = (blockIdx.x * blockDim.x + threadIdx.x) >> 5;
    int lane = threadIdx.x & 31;
    if (warp >= Nn) return;
    const uint32_t* rowbm = &bm[warp * WPR];
    uint32_t w[4]; int c = 0;
#pragma unroll
    for (int k = 0; k < 4; k++) { w[k] = rowbm[lane*4 + k]; c += __popc(w[k]); }
    int incl = c;
#pragma unroll
    for (int d = 1; d < 32; d <<= 1) {
        int t = __shfl_up_sync(0xFFFFFFFFu, incl, d);
        if (lane >= d) incl += t;
    }
    int total = __shfl_sync(0xFFFFFFFFu, incl, 31);
    int off = incl - c;
    int* dst = &colsOut[warp * SLOTS];
#pragma unroll
    for (int k = 0; k < 4; k++) {
        uint32_t m = w[k];
        int base = (lane*4 + k) << 5;
        while (m) { int b = __ffs(m) - 1; m &= m - 1; dst[off++] = base + b; }
    }
    if (lane == 0) {
        cntOut[warp] = total;
        if (writeStats) {
            float deg = (float)(total + 1);
            g_dinv[warp] = rsqrtf(deg);
            g_v[warp]    = sqrtf(deg);
        }
    }
}

// ---------------- left Perron eigenvector ----------------
__global__ void k_uinit() {
    int i = blockIdx.x * blockDim.x + threadIdx.x;
    if (i < Nn) g_u[i] = 1.0f;
}

__global__ void k_power(const float* __restrict__ uin, float* __restrict__ uout) {
    int warp = (blockIdx.x * blockDim.x + threadIdx.x) >> 5;
    int lane = threadIdx.x & 31;
    if (warp >= Nn) return;
    int cnt = g_cntT[warp];
    const int* cols = &g_colsT[warp * SLOTS];
    float s = 0.f;
    for (int k = lane; k < cnt; k += 32) {
        int j = cols[k];
        s += g_dinv[j] * uin[j];
    }
#pragma unroll
    for (int d = 16; d; d >>= 1) s += __shfl_down_sync(0xFFFFFFFFu, s, d);
    if (lane == 0) {
        float di = g_dinv[warp];
        uout[warp] = di * (s + di * uin[warp]);
    }
}

__global__ void k_dot() {
    __shared__ float sh[32];
    int t = threadIdx.x;
    float s = 0.f;
    for (int i = t; i < Nn; i += 1024) s += g_u[i] * g_v[i];
#pragma unroll
    for (int d = 16; d; d >>= 1) s += __shfl_down_sync(0xFFFFFFFFu, s, d);
    if ((t & 31) == 0) sh[t >> 5] = s;
    __syncthreads();
    if (t < 32) {
        s = sh[t];
#pragma unroll
        for (int d = 16; d; d >>= 1) s += __shfl_down_sync(0xFFFFFFFFu, s, d);
        if (t == 0) g_qscale = 1.0f / s;
    }
}

// ---------------- q = (u^T R) * qscale ----------------
__global__ void k_qzero() { g_q[threadIdx.x] = 0.f; }

__global__ void k_qaccum(const float* __restrict__ R) {
    int c = threadIdx.x;
    int r0 = blockIdx.x * 128;
    float s = 0.f;
    for (int k = 0; k < 128; k++)
        s += g_u[r0 + k] * R[(long)(r0 + k) * Dd + c];
    atomicAdd(&g_q[c], s);
}

__global__ void k_qfin() { g_q[threadIdx.x] *= g_qscale; }

// R'[i,c] = R[i,c] - v_i * q[c]   -> fp32 (g_A) and bf16 (g_bf0)
__global__ void k_r1(const float4* __restrict__ R, float4* __restrict__ Rp,
                     uint2* __restrict__ Rb) {
    int i = blockIdx.x * blockDim.x + threadIdx.x;
    int row = i >> 7, c4 = i & 127;
    float vr = g_v[row];
    float4 q = ((const float4*)g_q)[c4];
    float4 x = R[i];
    x.x -= vr * q.x; x.y -= vr * q.y; x.z -= vr * q.z; x.w -= vr * q.w;
    Rp[i] = x;
    __nv_bfloat162 p0 = __float22bfloat162_rn(make_float2(x.x, x.y));
    __nv_bfloat162 p1 = __float22bfloat162_rn(make_float2(x.z, x.w));
    uint2 o; o.x = *(uint32_t*)&p0; o.y = *(uint32_t*)&p1;
    Rb[i] = o;
}

// ---------------- fp32 SpMM (R pass) ----------------
__global__ __launch_bounds__(128) void k_matvec_f32(
    const float4* __restrict__ in, const float4* __restrict__ base,
    float4* __restrict__ out, float a, float b)
{
    int row = blockIdx.x;
    int col = threadIdx.x;
    int cnt = g_cnt[row];
    float di = g_dinv[row];
    const int* cols = &g_cols[row * SLOTS];
    long idx = (long)row * D4 + col;

    float4 sv = __ldg(&in[idx]);
    float4 s;
    s.x = di * sv.x; s.y = di * sv.y; s.z = di * sv.z; s.w = di * sv.w;

    int k = 0;
    for (; k + 4 <= cnt; k += 4) {
        int j0 = __ldg(&cols[k]),   j1 = __ldg(&cols[k+1]);
        int j2 = __ldg(&cols[k+2]), j3 = __ldg(&cols[k+3]);
        float w0 = __ldg(&g_dinv[j0]), w1 = __ldg(&g_dinv[j1]);
        float w2 = __ldg(&g_dinv[j2]), w3 = __ldg(&g_dinv[j3]);
        float4 v0 = __ldg(&in[(long)j0 * D4 + col]);
        float4 v1 = __ldg(&in[(long)j1 * D4 + col]);
        float4 v2 = __ldg(&in[(long)j2 * D4 + col]);
        float4 v3 = __ldg(&in[(long)j3 * D4 + col]);
        s.x += w0*v0.x + w1*v1.x + w2*v2.x + w3*v3.x;
        s.y += w0*v0.y + w1*v1.y + w2*v2.y + w3*v3.y;
        s.z += w0*v0.z + w1*v1.z + w2*v2.z + w3*v3.z;
        s.w += w0*v0.w + w1*v1.w + w2*v2.w + w3*v3.w;
    }
    for (; k < cnt; k++) {
        int j = __ldg(&cols[k]);
        float w = __ldg(&g_dinv[j]);
        float4 v = __ldg(&in[(long)j * D4 + col]);
        s.x += w*v.x; s.y += w*v.y; s.z += w*v.z; s.w += w*v.w;
    }
    float4 bs = __ldg(&base[idx]);
    float bd = b * di;
    float4 o;
    o.x = a*bs.x + bd*s.x; o.y = a*bs.y + bd*s.y;
    o.z = a*bs.z + bd*s.z; o.w = a*bs.w + bd*s.w;
    out[idx] = o;
}

// ---------------- bf16-gather SpMM (bulk passes) ----------------
// out = a*base + b*dinv_i*(sum_j dinv_j*in_bf[j] + dinv_i*in_bf[i]) + r*v_i*q
// writes bf16 (outb != 0) for middle passes, fp32 (outf != 0) for final.
__global__ __launch_bounds__(128) void k_matvec_bf(
    const uint2* __restrict__ inb, const float4* __restrict__ base,
    float4* __restrict__ outf, uint2* __restrict__ outb,
    float a, float b, float r)
{
    int row = blockIdx.x;
    int col = threadIdx.x;
    int cnt = g_cnt[row];
    float di = g_dinv[row];
    const int* cols = &g_cols[row * SLOTS];
    long idx = (long)row * D4 + col;

    uint2 sraw = __ldg(&inb[idx]);
    float2 sf0 = __bfloat1622float2(*(__nv_bfloat162*)&sraw.x);
    float2 sf1 = __bfloat1622float2(*(__nv_bfloat162*)&sraw.y);
    float4 s;
    s.x = di * sf0.x; s.y = di * sf0.y; s.z = di * sf1.x; s.w = di * sf1.y;

    int k = 0;
    for (; k + 4 <= cnt; k += 4) {
        int j0 = __ldg(&cols[k]),   j1 = __ldg(&cols[k+1]);
        int j2 = __ldg(&cols[k+2]), j3 = __ldg(&cols[k+3]);
        float w0 = __ldg(&g_dinv[j0]), w1 = __ldg(&g_dinv[j1]);
        float w2 = __ldg(&g_dinv[j2]), w3 = __ldg(&g_dinv[j3]);
        uint2 r0 = __ldg(&inb[(long)j0 * D4 + col]);
        uint2 r1 = __ldg(&inb[(long)j1 * D4 + col]);
        uint2 r2 = __ldg(&inb[(long)j2 * D4 + col]);
        uint2 r3 = __ldg(&inb[(long)j3 * D4 + col]);
        float2 a0 = __bfloat1622float2(*(__nv_bfloat162*)&r0.x);
        float2 b0 = __bfloat1622float2(*(__nv_bfloat162*)&r0.y);
        float2 a1 = __bfloat1622float2(*(__nv_bfloat162*)&r1.x);
        float2 b1 = __bfloat1622float2(*(__nv_bfloat162*)&r1.y);
        float2 a2 = __bfloat1622float2(*(__nv_bfloat162*)&r2.x);
        float2 b2 = __bfloat1622float2(*(__nv_bfloat162*)&r2.y);
        float2 a3 = __bfloat1622float2(*(__nv_bfloat162*)&r3.x);
        float2 b3 = __bfloat1622float2(*(__nv_bfloat162*)&r3.y);
        s.x += w0*a0.x + w1*a1.x + w2*a2.x + w3*a3.x;
        s.y += w0*a0.y + w1*a1.y + w2*a2.y + w3*a3.y;
        s.z += w0*b0.x + w1*b1.x + w2*b2.x + w3*b3.x;
        s.w += w0*b0.y + w1*b1.y + w2*b2.y + w3*b3.y;
    }
    for (; k < cnt; k++) {
        int j = __ldg(&cols[k]);
        float w = __ldg(&g_dinv[j]);
        uint2 rr = __ldg(&inb[(long)j * D4 + col]);
        float2 f0 = __bfloat1622float2(*(__nv_bfloat162*)&rr.x);
        float2 f1 = __bfloat1622float2(*(__nv_bfloat162*)&rr.y);
        s.x += w*f0.x; s.y += w*f0.y; s.z += w*f1.x; s.w += w*f1.y;
    }
    float4 bs = __ldg(&base[idx]);
    float bd = b * di;
    float rv = r * g_v[row];
    float4 q = ((const float4*)g_q)[col];
    float4 o;
    o.x = a*bs.x + bd*s.x + rv*q.x;
    o.y = a*bs.y + bd*s.y + rv*q.y;
    o.z = a*bs.z + bd*s.z + rv*q.z;
    o.w = a*bs.w + bd*s.w + rv*q.w;
    if (outf) outf[idx] = o;
    if (outb) {
        __nv_bfloat162 p0 = __float22bfloat162_rn(make_float2(o.x, o.y));
        __nv_bfloat162 p1 = __float22bfloat162_rn(make_float2(o.z, o.w));
        uint2 ob; ob.x = *(uint32_t*)&p0; ob.y = *(uint32_t*)&p1;
        outb[idx] = ob;
    }
}

// ---------------- launch ----------------
extern "C" void kernel_launch(void* const* d_in, const int* in_sizes, int n_in,
                              void* d_out, int out_size) {
    const float* x    = (const float*)d_in[0];
    const void*  eraw = d_in[1];
    if (in_sizes[0] != Nn * Dd) { x = (const float*)d_in[1]; eraw = d_in[0]; }
    const int* ei32 = (const int*)eraw;
    float4*    yo   = (float4*)d_out;

    float *pR, *pA;
    cudaGetSymbolAddress((void**)&pR, g_R);
    cudaGetSymbolAddress((void**)&pA, g_A);
    uint2 *pbf0, *pbf1;
    cudaGetSymbolAddress((void**)&pbf0, g_bf0);
    cudaGetSymbolAddress((void**)&pbf1, g_bf1);
    float *pu, *pu2;
    cudaGetSymbolAddress((void**)&pu,  g_u);
    cudaGetSymbolAddress((void**)&pu2, g_u2);
    uint32_t *pbm, *pbmT;
    cudaGetSymbolAddress((void**)&pbm,  g_bm);
    cudaGetSymbolAddress((void**)&pbmT, g_bmT);
    int *pcols, *pcolsT, *pcnt, *pcntT;
    cudaGetSymbolAddress((void**)&pcols,  g_cols);
    cudaGetSymbolAddress((void**)&pcolsT, g_colsT);
    cudaGetSymbolAddress((void**)&pcnt,   g_cnt);
    cudaGetSymbolAddress((void**)&pcntT,  g_cntT);

    // adjacency structure (dedup) forward + transpose
    k_zero_bitmaps<<<2048, 256>>>();
    k_sniff<<<1, 32>>>(ei32);
    k_scatter2<<<NE / 256, 256>>>(ei32);
    k_build<<<Nn/8, 256>>>(pbm,  pcols,  pcnt,  1);
    k_build<<<Nn/8, 256>>>(pbmT, pcolsT, pcntT, 0);

    // left Perron eigenvector u
    k_uinit<<<4, 1024>>>();
    for (int i = 0; i < NPOW / 2; i++) {
        k_power<<<128, 1024>>>(pu,  pu2);
        k_power<<<128, 1024>>>(pu2, pu);
    }
    k_dot<<<1, 1024>>>();

    // R = (I + 0.5*Ahat) X  (fp32)
    k_matvec_f32<<<Nn, 128>>>((const float4*)x, (const float4*)x, (float4*)pR,
                              1.0f, 0.5f);

    // q = u^T R / (u^T v);  R' = R - v q^T  (fp32 + bf16)
    k_qzero<<<1, Dd>>>();
    k_qaccum<<<32, Dd>>>(pR);
    k_qfin<<<1, Dd>>>();
    k_r1<<<2048, 256>>>((const float4*)pR, (float4*)pA, pbf0);

    // deflated Neumann, bf16 iterates:
    // acc <- R' + 0.6*Ahat*acc ; Y = v q^T + 0.4*acc_final
    uint2* bufs[2] = { pbf1, pbf0 };
    const uint2* in = pbf0;
    for (int i = 0; i < KBULK; i++) {
        bool last = (i == KBULK - 1);
        if (last) {
            k_matvec_bf<<<Nn, 128>>>(in, (const float4*)pA, yo, (uint2*)0,
                                     0.4f, 0.24f, 1.0f);
        } else {
            uint2* ob = bufs[i & 1];
            k_matvec_bf<<<Nn, 128>>>(in, (const float4*)pA, (float4*)0, ob,
                                     1.0f, 0.6f, 0.0f);
            in = ob;
        }
    }
}

// round 6
// speedup vs baseline: 5.6061x; 1.0750x over previous
#include <cuda_runtime.h>
#include <cuda_bf16.h>
#include <stdint.h>

#define Nn    4096
#define Dd    512
#define D4    128        // Dd/4
#define NE    131072
#define WPR   128
#define SLOTS 128
#define NPOW  4          // power iterations (even)

// ---------------- scratch ----------------
__device__ uint32_t g_bm [Nn * WPR];
__device__ uint32_t g_bmT[Nn * WPR];
__device__ int      g_cols [Nn * SLOTS];
__device__ int      g_colsT[Nn * SLOTS];
__device__ int      g_cnt [Nn];
__device__ int      g_cntT[Nn];
__device__ float    g_dinv[Nn];
__device__ float    g_v[Nn];
__device__ float    g_u[Nn], g_u2[Nn];
__device__ float    g_q[Dd];
__device__ float    g_Af[Nn * Dd];       // R' fp32 (final-pass base)
__device__ uint2    g_Ab[Nn * D4];       // R' bf16 (middle-pass base + iterate0)
__device__ uint2    g_Xb[Nn * D4];       // X bf16 (R-pass gathers)
__device__ uint2    g_bf0[Nn * D4];      // iterate ping
__device__ uint2    g_bf1[Nn * D4];      // iterate pong
__device__ int      g_is64;

// ---------------- helpers ----------------
__device__ __forceinline__ float4 bf2f4(uint2 r) {
    float2 a = __bfloat1622float2(*(__nv_bfloat162*)&r.x);
    float2 b = __bfloat1622float2(*(__nv_bfloat162*)&r.y);
    return make_float4(a.x, a.y, b.x, b.y);
}
__device__ __forceinline__ uint2 f42bf(float4 x) {
    __nv_bfloat162 p0 = __float22bfloat162_rn(make_float2(x.x, x.y));
    __nv_bfloat162 p1 = __float22bfloat162_rn(make_float2(x.z, x.w));
    uint2 o; o.x = *(uint32_t*)&p0; o.y = *(uint32_t*)&p1;
    return o;
}

// ---------------- setup ----------------
__global__ void k_zero_bitmaps() {
    int i = blockIdx.x * blockDim.x + threadIdx.x;
    if (i < Nn * WPR / 4)  ((uint4*)g_bm )[i]            = make_uint4(0,0,0,0);
    else                   ((uint4*)g_bmT)[i - Nn*WPR/4] = make_uint4(0,0,0,0);
}

__global__ void k_sniff(const int* __restrict__ ei32) {
    if (threadIdx.x == 0 && blockIdx.x == 0) {
        int acc = 0;
        for (int k = 1; k < 2048; k += 2) acc |= ei32[k];
        g_is64 = (acc == 0) ? 1 : 0;
    }
}

__global__ void k_scatter2(const int* __restrict__ ei32) {
    int e = blockIdx.x * blockDim.x + threadIdx.x;
    if (e < NE) {
        int s, d;
        if (g_is64) { s = ei32[2*e]; d = ei32[2*(NE+e)]; }
        else        { s = ei32[e];   d = ei32[NE+e]; }
        atomicOr(&g_bm [s * WPR + (d >> 5)], 1u << (d & 31));
        atomicOr(&g_bmT[d * WPR + (s >> 5)], 1u << (s & 31));
    }
}

// forward rows [0,Nn), transpose rows [Nn,2Nn) in one launch
__global__ void k_build_both() {
    int warp = (blockIdx.x * blockDim.x + threadIdx.x) >> 5;
    int lane = threadIdx.x & 31;
    if (warp >= 2 * Nn) return;
    int fwd = (warp < Nn);
    int row = fwd ? warp : warp - Nn;
    const uint32_t* rowbm = fwd ? &g_bm[row * WPR] : &g_bmT[row * WPR];
    int* dst  = fwd ? &g_cols[row * SLOTS] : &g_colsT[row * SLOTS];
    uint32_t w[4]; int c = 0;
#pragma unroll
    for (int k = 0; k < 4; k++) { w[k] = rowbm[lane*4 + k]; c += __popc(w[k]); }
    int incl = c;
#pragma unroll
    for (int d = 1; d < 32; d <<= 1) {
        int t = __shfl_up_sync(0xFFFFFFFFu, incl, d);
        if (lane >= d) incl += t;
    }
    int total = __shfl_sync(0xFFFFFFFFu, incl, 31);
    int off = incl - c;
#pragma unroll
    for (int k = 0; k < 4; k++) {
        uint32_t m = w[k];
        int base = (lane*4 + k) << 5;
        while (m) { int b = __ffs(m) - 1; m &= m - 1; dst[off++] = base + b; }
    }
    if (lane == 0) {
        if (fwd) {
            g_cnt[row] = total;
            float deg = (float)(total + 1);
            g_dinv[row] = rsqrtf(deg);
            g_v[row]    = sqrtf(deg);
        } else {
            g_cntT[row] = total;
        }
    }
}

// X fp32 -> bf16
__global__ void k_x2bf(const float4* __restrict__ x, uint2* __restrict__ xb) {
    int i = blockIdx.x * blockDim.x + threadIdx.x;   // 524288
    xb[i] = f42bf(x[i]);
}

// ---------------- left Perron eigenvector ----------------
__global__ void k_uinit() {
    int i = blockIdx.x * blockDim.x + threadIdx.x;
    if (i < Nn) g_u[i] = 1.0f;
}

__global__ void k_power(const float* __restrict__ uin, float* __restrict__ uout) {
    int warp = (blockIdx.x * blockDim.x + threadIdx.x) >> 5;
    int lane = threadIdx.x & 31;
    if (warp >= Nn) return;
    int cnt = g_cntT[warp];
    const int* cols = &g_colsT[warp * SLOTS];
    float s = 0.f;
    for (int k = lane; k < cnt; k += 32) {
        int j = cols[k];
        s += g_dinv[j] * uin[j];
    }
#pragma unroll
    for (int d = 16; d; d >>= 1) s += __shfl_down_sync(0xFFFFFFFFu, s, d);
    if (lane == 0) {
        float di = g_dinv[warp];
        uout[warp] = di * (s + di * uin[warp]);
    }
}

// ---------------- q = 1.5 * u^T X / (u^T v) ----------------
__global__ void k_qzero() { g_q[threadIdx.x] = 0.f; }

__global__ void k_qaccum(const float* __restrict__ X) {
    int c = threadIdx.x;
    int r0 = blockIdx.x * 128;
    float s = 0.f;
    for (int k = 0; k < 128; k++)
        s += g_u[r0 + k] * X[(long)(r0 + k) * Dd + c];
    atomicAdd(&g_q[c], s);
}

// scale q by 1.5/(u^T v) -- dot computed in-block.
// NOTE: final warp reduction runs with a FULL warp (t < 32) and fully
// initialized sh[] -- partial-warp shfl with full mask hangs sm_70+.
__global__ void k_qfin() {
    __shared__ float sh[32];
    __shared__ float scale;
    int t = threadIdx.x;      // 512 threads = 16 warps
    if (t < 32) sh[t] = 0.f;
    __syncthreads();
    float s = 0.f;
    for (int i = t; i < Nn; i += 512) s += g_u[i] * g_v[i];
#pragma unroll
    for (int d = 16; d; d >>= 1) s += __shfl_down_sync(0xFFFFFFFFu, s, d);
    if ((t & 31) == 0) sh[t >> 5] = s;
    __syncthreads();
    if (t < 32) {
        s = sh[t];
#pragma unroll
        for (int d = 16; d; d >>= 1) s += __shfl_down_sync(0xFFFFFFFFu, s, d);
        if (t == 0) scale = 1.5f / s;
    }
    __syncthreads();
    g_q[t] *= scale;
}

// ---------------- R pass: R' = (I + 0.5*Ahat)X - v q^T ----------------
// gathers bf16 X; self + rank-1 in fp32; writes fp32 + bf16 R'
__global__ __launch_bounds__(128) void k_Rpass(
    const float4* __restrict__ xf, const uint2* __restrict__ xb,
    float4* __restrict__ outf, uint2* __restrict__ outb)
{
    int row = blockIdx.x;
    int col = threadIdx.x;
    int cnt = g_cnt[row];
    float di = g_dinv[row];
    const int* cols = &g_cols[row * SLOTS];
    long idx = (long)row * D4 + col;

    float4 xi = __ldg(&xf[idx]);
    float4 s;
    s.x = di * xi.x; s.y = di * xi.y; s.z = di * xi.z; s.w = di * xi.w;

    int k = 0;
    for (; k + 4 <= cnt; k += 4) {
        int j0 = __ldg(&cols[k]),   j1 = __ldg(&cols[k+1]);
        int j2 = __ldg(&cols[k+2]), j3 = __ldg(&cols[k+3]);
        float w0 = __ldg(&g_dinv[j0]), w1 = __ldg(&g_dinv[j1]);
        float w2 = __ldg(&g_dinv[j2]), w3 = __ldg(&g_dinv[j3]);
        float4 v0 = bf2f4(__ldg(&xb[(long)j0 * D4 + col]));
        float4 v1 = bf2f4(__ldg(&xb[(long)j1 * D4 + col]));
        float4 v2 = bf2f4(__ldg(&xb[(long)j2 * D4 + col]));
        float4 v3 = bf2f4(__ldg(&xb[(long)j3 * D4 + col]));
        s.x += w0*v0.x + w1*v1.x + w2*v2.x + w3*v3.x;
        s.y += w0*v0.y + w1*v1.y + w2*v2.y + w3*v3.y;
        s.z += w0*v0.z + w1*v1.z + w2*v2.z + w3*v3.z;
        s.w += w0*v0.w + w1*v1.w + w2*v2.w + w3*v3.w;
    }
    for (; k < cnt; k++) {
        int j = __ldg(&cols[k]);
        float w = __ldg(&g_dinv[j]);
        float4 v = bf2f4(__ldg(&xb[(long)j * D4 + col]));
        s.x += w*v.x; s.y += w*v.y; s.z += w*v.z; s.w += w*v.w;
    }
    float hd = 0.5f * di;
    float vr = g_v[row];
    float4 q = ((const float4*)g_q)[col];
    float4 o;
    o.x = xi.x + hd*s.x - vr*q.x;
    o.y = xi.y + hd*s.y - vr*q.y;
    o.z = xi.z + hd*s.z - vr*q.z;
    o.w = xi.w + hd*s.w - vr*q.w;
    outf[idx] = o;
    outb[idx] = f42bf(o);
}

// ---------------- middle bulk pass (all-bf16) ----------------
// out_bf = base_bf + 0.6*dinv_i*(sum_j dinv_j*in[j] + dinv_i*in[i])
__global__ __launch_bounds__(128) void k_bulk(
    const uint2* __restrict__ inb, const uint2* __restrict__ baseb,
    uint2* __restrict__ outb)
{
    int row = blockIdx.x;
    int col = threadIdx.x;
    int cnt = g_cnt[row];
    float di = g_dinv[row];
    const int* cols = &g_cols[row * SLOTS];
    long idx = (long)row * D4 + col;

    float4 sv = bf2f4(__ldg(&inb[idx]));
    float4 s;
    s.x = di * sv.x; s.y = di * sv.y; s.z = di * sv.z; s.w = di * sv.w;

    int k = 0;
    for (; k + 4 <= cnt; k += 4) {
        int j0 = __ldg(&cols[k]),   j1 = __ldg(&cols[k+1]);
        int j2 = __ldg(&cols[k+2]), j3 = __ldg(&cols[k+3]);
        float w0 = __ldg(&g_dinv[j0]), w1 = __ldg(&g_dinv[j1]);
        float w2 = __ldg(&g_dinv[j2]), w3 = __ldg(&g_dinv[j3]);
        float4 v0 = bf2f4(__ldg(&inb[(long)j0 * D4 + col]));
        float4 v1 = bf2f4(__ldg(&inb[(long)j1 * D4 + col]));
        float4 v2 = bf2f4(__ldg(&inb[(long)j2 * D4 + col]));
        float4 v3 = bf2f4(__ldg(&inb[(long)j3 * D4 + col]));
        s.x += w0*v0.x + w1*v1.x + w2*v2.x + w3*v3.x;
        s.y += w0*v0.y + w1*v1.y + w2*v2.y + w3*v3.y;
        s.z += w0*v0.z + w1*v1.z + w2*v2.z + w3*v3.z;
        s.w += w0*v0.w + w1*v1.w + w2*v2.w + w3*v3.w;
    }
    for (; k < cnt; k++) {
        int j = __ldg(&cols[k]);
        float w = __ldg(&g_dinv[j]);
        float4 v = bf2f4(__ldg(&inb[(long)j * D4 + col]));
        s.x += w*v.x; s.y += w*v.y; s.z += w*v.z; s.w += w*v.w;
    }
    float4 bs = bf2f4(__ldg(&baseb[idx]));
    float bd = 0.6f * di;
    float4 o;
    o.x = bs.x + bd*s.x; o.y = bs.y + bd*s.y;
    o.z = bs.z + bd*s.z; o.w = bs.w + bd*s.w;
    outb[idx] = f42bf(o);
}

// ---------------- final pass ----------------
// Y = 0.4*basef + 0.24*dinv_i*(sum_j dinv_j*in[j] + dinv_i*in[i]) + v_i*q
__global__ __launch_bounds__(128) void k_final(
    const uint2* __restrict__ inb, const float4* __restrict__ basef,
    float4* __restrict__ out)
{
    int row = blockIdx.x;
    int col = threadIdx.x;
    int cnt = g_cnt[row];
    float di = g_dinv[row];
    const int* cols = &g_cols[row * SLOTS];
    long idx = (long)row * D4 + col;

    float4 sv = bf2f4(__ldg(&inb[idx]));
    float4 s;
    s.x = di * sv.x; s.y = di * sv.y; s.z = di * sv.z; s.w = di * sv.w;

    int k = 0;
    for (; k + 4 <= cnt; k += 4) {
        int j0 = __ldg(&cols[k]),   j1 = __ldg(&cols[k+1]);
        int j2 = __ldg(&cols[k+2]), j3 = __ldg(&cols[k+3]);
        float w0 = __ldg(&g_dinv[j0]), w1 = __ldg(&g_dinv[j1]);
        float w2 = __ldg(&g_dinv[j2]), w3 = __ldg(&g_dinv[j3]);
        float4 v0 = bf2f4(__ldg(&inb[(long)j0 * D4 + col]));
        float4 v1 = bf2f4(__ldg(&inb[(long)j1 * D4 + col]));
        float4 v2 = bf2f4(__ldg(&inb[(long)j2 * D4 + col]));
        float4 v3 = bf2f4(__ldg(&inb[(long)j3 * D4 + col]));
        s.x += w0*v0.x + w1*v1.x + w2*v2.x + w3*v3.x;
        s.y += w0*v0.y + w1*v1.y + w2*v2.y + w3*v3.y;
        s.z += w0*v0.z + w1*v1.z + w2*v2.z + w3*v3.z;
        s.w += w0*v0.w + w1*v1.w + w2*v2.w + w3*v3.w;
    }
    for (; k < cnt; k++) {
        int j = __ldg(&cols[k]);
        float w = __ldg(&g_dinv[j]);
        float4 v = bf2f4(__ldg(&inb[(long)j * D4 + col]));
        s.x += w*v.x; s.y += w*v.y; s.z += w*v.z; s.w += w*v.w;
    }
    float4 bs = __ldg(&basef[idx]);
    float bd = 0.24f * di;
    float rv = g_v[row];
    float4 q = ((const float4*)g_q)[col];
    float4 o;
    o.x = 0.4f*bs.x + bd*s.x + rv*q.x;
    o.y = 0.4f*bs.y + bd*s.y + rv*q.y;
    o.z = 0.4f*bs.z + bd*s.z + rv*q.z;
    o.w = 0.4f*bs.w + bd*s.w + rv*q.w;
    out[idx] = o;
}

// ---------------- launch ----------------
extern "C" void kernel_launch(void* const* d_in, const int* in_sizes, int n_in,
                              void* d_out, int out_size) {
    const float* x    = (const float*)d_in[0];
    const void*  eraw = d_in[1];
    if (in_sizes[0] != Nn * Dd) { x = (const float*)d_in[1]; eraw = d_in[0]; }
    const int* ei32 = (const int*)eraw;
    float4*    yo   = (float4*)d_out;

    float *pAf;  cudaGetSymbolAddress((void**)&pAf, g_Af);
    uint2 *pAb;  cudaGetSymbolAddress((void**)&pAb, g_Ab);
    uint2 *pXb;  cudaGetSymbolAddress((void**)&pXb, g_Xb);
    uint2 *pbf0; cudaGetSymbolAddress((void**)&pbf0, g_bf0);
    uint2 *pbf1; cudaGetSymbolAddress((void**)&pbf1, g_bf1);
    float *pu;   cudaGetSymbolAddress((void**)&pu,  g_u);
    float *pu2;  cudaGetSymbolAddress((void**)&pu2, g_u2);

    // adjacency structure (dedup), forward + transpose
    k_zero_bitmaps<<<2048, 256>>>();
    k_sniff<<<1, 32>>>(ei32);
    k_scatter2<<<NE / 256, 256>>>(ei32);
    k_build_both<<<2 * Nn / 8, 256>>>();

    // X -> bf16 (for R-pass gathers)
    k_x2bf<<<2048, 256>>>((const float4*)x, pXb);

    // left Perron eigenvector u
    k_uinit<<<4, 1024>>>();
    for (int i = 0; i < NPOW / 2; i++) {
        k_power<<<128, 1024>>>(pu,  pu2);
        k_power<<<128, 1024>>>(pu2, pu);
    }

    // q = 1.5 * u^T X / (u^T v)
    k_qzero<<<1, Dd>>>();
    k_qaccum<<<32, Dd>>>(x);
    k_qfin<<<1, Dd>>>();

    // R' = (I + 0.5*Ahat)X - v q^T   (fp32 + bf16)
    k_Rpass<<<Nn, 128>>>((const float4*)x, pXb, (float4*)pAf, pAb);

    // 3 middle bulk passes: acc <- R' + 0.6*Ahat*acc  (all bf16)
    k_bulk<<<Nn, 128>>>(pAb,  pAb, pbf0);
    k_bulk<<<Nn, 128>>>(pbf0, pAb, pbf1);
    k_bulk<<<Nn, 128>>>(pbf1, pAb, pbf0);

    // final: Y = v q^T + 0.4*(R' + 0.6*Ahat*acc)
    k_final<<<Nn, 128>>>(pbf0, (const float4*)pAf, yo);
}

// round 7
// speedup vs baseline: 7.4818x; 1.3346x over previous
#include <cuda_runtime.h>
#include <cuda_bf16.h>
#include <stdint.h>

#define Nn    4096
#define Dd    512
#define D4    128        // Dd/4
#define NE    131072
#define WPR   128
#define SLOTS 128
#define UPBLK 128        // blocks in fused u-kernel (must be < #SMs for residency)

// ---------------- scratch ----------------
__device__ uint32_t g_bm [Nn * WPR];
__device__ uint32_t g_bmT[Nn * WPR];
__device__ int      g_cols [Nn * SLOTS];
__device__ int      g_colsT[Nn * SLOTS];
__device__ int      g_cnt [Nn];
__device__ int      g_cntT[Nn];
__device__ float    g_dinv[Nn];
__device__ float    g_v[Nn];
__device__ float    g_u[Nn], g_u2[Nn];
__device__ float    g_q[Dd];
__device__ float    g_Af[Nn * Dd];       // R' fp32 (final-pass base)
__device__ uint2    g_Ab[Nn * D4];       // R' bf16 (middle-pass base + iterate0)
__device__ uint2    g_Xb[Nn * D4];       // X bf16 (R-pass gathers)
__device__ uint2    g_bf0[Nn * D4];      // iterate ping
__device__ uint2    g_bf1[Nn * D4];      // iterate pong
__device__ int      g_is64;
__device__ int      g_bar[8];            // grid-barrier counters (re-zeroed per call)

// ---------------- helpers ----------------
__device__ __forceinline__ float4 bf2f4(uint2 r) {
    float2 a = __bfloat1622float2(*(__nv_bfloat162*)&r.x);
    float2 b = __bfloat1622float2(*(__nv_bfloat162*)&r.y);
    return make_float4(a.x, a.y, b.x, b.y);
}
__device__ __forceinline__ uint2 f42bf(float4 x) {
    __nv_bfloat162 p0 = __float22bfloat162_rn(make_float2(x.x, x.y));
    __nv_bfloat162 p1 = __float22bfloat162_rn(make_float2(x.z, x.w));
    uint2 o; o.x = *(uint32_t*)&p0; o.y = *(uint32_t*)&p1;
    return o;
}
// software grid barrier: all UPBLK blocks must be co-resident
__device__ __forceinline__ void gridbar(int idx, int nb) {
    __syncthreads();
    if (threadIdx.x == 0) {
        __threadfence();
        atomicAdd(&g_bar[idx], 1);
        while (atomicAdd(&g_bar[idx], 0) < nb) {}
    }
    __syncthreads();
}

// ---------------- init: zero bitmaps + barriers + q, u=1, sniff dtype ----------------
__global__ void k_init(const int* __restrict__ ei32) {
    int gid = blockIdx.x * blockDim.x + threadIdx.x;   // 1024 x 256 = 262144
    if (gid < Nn * WPR / 4)  ((uint4*)g_bm )[gid]                 = make_uint4(0,0,0,0);
    else                     ((uint4*)g_bmT)[gid - Nn*WPR/4]      = make_uint4(0,0,0,0);
    if (gid < Nn)  g_u[gid] = 1.0f;
    if (gid < Dd)  g_q[gid] = 0.0f;
    if (gid < 8)   g_bar[gid] = 0;
    // sniff int64 vs int32: for int64 values < 4096, all odd 32-bit words are 0
    if (blockIdx.x == 1023 && threadIdx.x < 32) {
        int t = threadIdx.x, acc = 0;
        for (int k = t; k < 1024; k += 32) acc |= ei32[2*k + 1];
#pragma unroll
        for (int d = 16; d; d >>= 1) acc |= __shfl_xor_sync(0xFFFFFFFFu, acc, d);
        if (t == 0) g_is64 = (acc == 0);
    }
}

__global__ void k_scatter2(const int* __restrict__ ei32) {
    int e = blockIdx.x * blockDim.x + threadIdx.x;
    if (e < NE) {
        int s, d;
        if (g_is64) { s = ei32[2*e]; d = ei32[2*(NE+e)]; }
        else        { s = ei32[e];   d = ei32[NE+e]; }
        atomicOr(&g_bm [s * WPR + (d >> 5)], 1u << (d & 31));
        atomicOr(&g_bmT[d * WPR + (s >> 5)], 1u << (s & 31));
    }
}

// build fwd+transpose CSR (blocks 0..1023) and X->bf16 (blocks 1024..3071)
__global__ void k_build_x2bf(const float4* __restrict__ x) {
    if (blockIdx.x < 1024) {
        int warp = (blockIdx.x * blockDim.x + threadIdx.x) >> 5;   // 0..8191
        int lane = threadIdx.x & 31;
        int fwd = (warp < Nn);
        int row = fwd ? warp : warp - Nn;
        const uint32_t* rowbm = fwd ? &g_bm[row * WPR] : &g_bmT[row * WPR];
        int* dst  = fwd ? &g_cols[row * SLOTS] : &g_colsT[row * SLOTS];
        uint32_t w[4]; int c = 0;
#pragma unroll
        for (int k = 0; k < 4; k++) { w[k] = rowbm[lane*4 + k]; c += __popc(w[k]); }
        int incl = c;
#pragma unroll
        for (int d = 1; d < 32; d <<= 1) {
            int t = __shfl_up_sync(0xFFFFFFFFu, incl, d);
            if (lane >= d) incl += t;
        }
        int total = __shfl_sync(0xFFFFFFFFu, incl, 31);
        int off = incl - c;
#pragma unroll
        for (int k = 0; k < 4; k++) {
            uint32_t m = w[k];
            int base = (lane*4 + k) << 5;
            while (m) { int b = __ffs(m) - 1; m &= m - 1; dst[off++] = base + b; }
        }
        if (lane == 0) {
            if (fwd) {
                g_cnt[row] = total;
                float deg = (float)(total + 1);
                g_dinv[row] = rsqrtf(deg);
                g_v[row]    = sqrtf(deg);
            } else {
                g_cntT[row] = total;
            }
        }
    } else {
        int i = (blockIdx.x - 1024) * blockDim.x + threadIdx.x;   // 0..524287
        g_Xb[i] = f42bf(x[i]);
    }
}

// ---------------- fused u-pipeline: 4 power iters + q = 1.5 u^T X/(u^T v) ----------
// grid = UPBLK blocks x 1024 threads, all co-resident; grid barriers inside.
__global__ __launch_bounds__(1024) void k_upower(const float* __restrict__ X) {
    int b    = blockIdx.x;
    int t    = threadIdx.x;
    int wid  = t >> 5;          // 32 warps
    int lane = t & 31;
    int rowsPerBlk = Nn / UPBLK;            // 32

    // 4 power iterations on Ahat^T: u -> u2 -> u -> u2 -> u
#pragma unroll
    for (int it = 0; it < 4; it++) {
        const float* src = (it & 1) ? g_u2 : g_u;
        float*       dst = (it & 1) ? g_u  : g_u2;
        int row = b * rowsPerBlk + wid;
        int cnt = g_cntT[row];
        const int* cols = &g_colsT[row * SLOTS];
        float s = 0.f;
        for (int k = lane; k < cnt; k += 32)
            s += g_dinv[cols[k]] * src[cols[k]];
#pragma unroll
        for (int d = 16; d; d >>= 1) s += __shfl_down_sync(0xFFFFFFFFu, s, d);
        if (lane == 0) {
            float di = g_dinv[row];
            dst[row] = di * (s + di * src[row]);
        }
        gridbar(it, UPBLK);
    }

    // qaccum: block b covers rows [b*32, b*32+32); thread t: col=t&511, half=t>>9
    {
        __shared__ float sh[Dd];
        int col  = t & 511;
        int half = t >> 9;
        int r0 = b * rowsPerBlk + half * 16;
        float s = 0.f;
        for (int k = 0; k < 16; k++)
            s += g_u[r0 + k] * __ldg(&X[(long)(r0 + k) * Dd + col]);
        if (half == 0) sh[col] = s;
        __syncthreads();
        if (half == 1) sh[col] += s;
        __syncthreads();
        if (t < Dd) atomicAdd(&g_q[t], sh[t]);
    }
    gridbar(4, UPBLK);

    // qfin on block 0: scale q by 1.5/(u.v)
    if (b == 0) {
        __shared__ float sh[32];
        __shared__ float scale;
        float s = 0.f;
        for (int i = t; i < Nn; i += 1024) s += g_u[i] * g_v[i];
#pragma unroll
        for (int d = 16; d; d >>= 1) s += __shfl_down_sync(0xFFFFFFFFu, s, d);
        if (lane == 0) sh[wid] = s;
        __syncthreads();
        if (t < 32) {
            s = sh[t];
#pragma unroll
            for (int d = 16; d; d >>= 1) s += __shfl_down_sync(0xFFFFFFFFu, s, d);
            if (t == 0) scale = 1.5f / s;
        }
        __syncthreads();
        if (t < Dd) g_q[t] *= scale;
    }
}

// ---------------- R pass: R' = (I + 0.5*Ahat)X - v q^T ----------------
__global__ __launch_bounds__(128) void k_Rpass(
    const float4* __restrict__ xf, const uint2* __restrict__ xb,
    float4* __restrict__ outf, uint2* __restrict__ outb)
{
    int row = blockIdx.x;
    int col = threadIdx.x;
    int cnt = g_cnt[row];
    float di = g_dinv[row];
    const int* cols = &g_cols[row * SLOTS];
    long idx = (long)row * D4 + col;

    float4 xi = __ldg(&xf[idx]);
    float4 s;
    s.x = di * xi.x; s.y = di * xi.y; s.z = di * xi.z; s.w = di * xi.w;

    int k = 0;
    for (; k + 4 <= cnt; k += 4) {
        int j0 = __ldg(&cols[k]),   j1 = __ldg(&cols[k+1]);
        int j2 = __ldg(&cols[k+2]), j3 = __ldg(&cols[k+3]);
        float w0 = __ldg(&g_dinv[j0]), w1 = __ldg(&g_dinv[j1]);
        float w2 = __ldg(&g_dinv[j2]), w3 = __ldg(&g_dinv[j3]);
        float4 v0 = bf2f4(__ldg(&xb[(long)j0 * D4 + col]));
        float4 v1 = bf2f4(__ldg(&xb[(long)j1 * D4 + col]));
        float4 v2 = bf2f4(__ldg(&xb[(long)j2 * D4 + col]));
        float4 v3 = bf2f4(__ldg(&xb[(long)j3 * D4 + col]));
        s.x += w0*v0.x + w1*v1.x + w2*v2.x + w3*v3.x;
        s.y += w0*v0.y + w1*v1.y + w2*v2.y + w3*v3.y;
        s.z += w0*v0.z + w1*v1.z + w2*v2.z + w3*v3.z;
        s.w += w0*v0.w + w1*v1.w + w2*v2.w + w3*v3.w;
    }
    for (; k < cnt; k++) {
        int j = __ldg(&cols[k]);
        float w = __ldg(&g_dinv[j]);
        float4 v = bf2f4(__ldg(&xb[(long)j * D4 + col]));
        s.x += w*v.x; s.y += w*v.y; s.z += w*v.z; s.w += w*v.w;
    }
    float hd = 0.5f * di;
    float vr = g_v[row];
    float4 q = ((const float4*)g_q)[col];
    float4 o;
    o.x = xi.x + hd*s.x - vr*q.x;
    o.y = xi.y + hd*s.y - vr*q.y;
    o.z = xi.z + hd*s.z - vr*q.z;
    o.w = xi.w + hd*s.w - vr*q.w;
    outf[idx] = o;
    outb[idx] = f42bf(o);
}

// ---------------- middle bulk pass (all-bf16) ----------------
__global__ __launch_bounds__(128) void k_bulk(
    const uint2* __restrict__ inb, const uint2* __restrict__ baseb,
    uint2* __restrict__ outb)
{
    int row = blockIdx.x;
    int col = threadIdx.x;
    int cnt = g_cnt[row];
    float di = g_dinv[row];
    const int* cols = &g_cols[row * SLOTS];
    long idx = (long)row * D4 + col;

    float4 sv = bf2f4(__ldg(&inb[idx]));
    float4 s;
    s.x = di * sv.x; s.y = di * sv.y; s.z = di * sv.z; s.w = di * sv.w;

    int k = 0;
    for (; k + 4 <= cnt; k += 4) {
        int j0 = __ldg(&cols[k]),   j1 = __ldg(&cols[k+1]);
        int j2 = __ldg(&cols[k+2]), j3 = __ldg(&cols[k+3]);
        float w0 = __ldg(&g_dinv[j0]), w1 = __ldg(&g_dinv[j1]);
        float w2 = __ldg(&g_dinv[j2]), w3 = __ldg(&g_dinv[j3]);
        float4 v0 = bf2f4(__ldg(&inb[(long)j0 * D4 + col]));
        float4 v1 = bf2f4(__ldg(&inb[(long)j1 * D4 + col]));
        float4 v2 = bf2f4(__ldg(&inb[(long)j2 * D4 + col]));
        float4 v3 = bf2f4(__ldg(&inb[(long)j3 * D4 + col]));
        s.x += w0*v0.x + w1*v1.x + w2*v2.x + w3*v3.x;
        s.y += w0*v0.y + w1*v1.y + w2*v2.y + w3*v3.y;
        s.z += w0*v0.z + w1*v1.z + w2*v2.z + w3*v3.z;
        s.w += w0*v0.w + w1*v1.w + w2*v2.w + w3*v3.w;
    }
    for (; k < cnt; k++) {
        int j = __ldg(&cols[k]);
        float w = __ldg(&g_dinv[j]);
        float4 v = bf2f4(__ldg(&inb[(long)j * D4 + col]));
        s.x += w*v.x; s.y += w*v.y; s.z += w*v.z; s.w += w*v.w;
    }
    float4 bs = bf2f4(__ldg(&baseb[idx]));
    float bd = 0.6f * di;
    float4 o;
    o.x = bs.x + bd*s.x; o.y = bs.y + bd*s.y;
    o.z = bs.z + bd*s.z; o.w = bs.w + bd*s.w;
    outb[idx] = f42bf(o);
}

// ---------------- final: Y = 0.4*R' + 0.24*Ahat*acc + v q^T ----------------
__global__ __launch_bounds__(128) void k_final(
    const uint2* __restrict__ inb, const float4* __restrict__ basef,
    float4* __restrict__ out)
{
    int row = blockIdx.x;
    int col = threadIdx.x;
    int cnt = g_cnt[row];
    float di = g_dinv[row];
    const int* cols = &g_cols[row * SLOTS];
    long idx = (long)row * D4 + col;

    float4 sv = bf2f4(__ldg(&inb[idx]));
    float4 s;
    s.x = di * sv.x; s.y = di * sv.y; s.z = di * sv.z; s.w = di * sv.w;

    int k = 0;
    for (; k + 4 <= cnt; k += 4) {
        int j0 = __ldg(&cols[k]),   j1 = __ldg(&cols[k+1]);
        int j2 = __ldg(&cols[k+2]), j3 = __ldg(&cols[k+3]);
        float w0 = __ldg(&g_dinv[j0]), w1 = __ldg(&g_dinv[j1]);
        float w2 = __ldg(&g_dinv[j2]), w3 = __ldg(&g_dinv[j3]);
        float4 v0 = bf2f4(__ldg(&inb[(long)j0 * D4 + col]));
        float4 v1 = bf2f4(__ldg(&inb[(long)j1 * D4 + col]));
        float4 v2 = bf2f4(__ldg(&inb[(long)j2 * D4 + col]));
        float4 v3 = bf2f4(__ldg(&inb[(long)j3 * D4 + col]));
        s.x += w0*v0.x + w1*v1.x + w2*v2.x + w3*v3.x;
        s.y += w0*v0.y + w1*v1.y + w2*v2.y + w3*v3.y;
        s.z += w0*v0.z + w1*v1.z + w2*v2.z + w3*v3.z;
        s.w += w0*v0.w + w1*v1.w + w2*v2.w + w3*v3.w;
    }
    for (; k < cnt; k++) {
        int j = __ldg(&cols[k]);
        float w = __ldg(&g_dinv[j]);
        float4 v = bf2f4(__ldg(&inb[(long)j * D4 + col]));
        s.x += w*v.x; s.y += w*v.y; s.z += w*v.z; s.w += w*v.w;
    }
    float4 bs = __ldg(&basef[idx]);
    float bd = 0.24f * di;
    float rv = g_v[row];
    float4 q = ((const float4*)g_q)[col];
    float4 o;
    o.x = 0.4f*bs.x + bd*s.x + rv*q.x;
    o.y = 0.4f*bs.y + bd*s.y + rv*q.y;
    o.z = 0.4f*bs.z + bd*s.z + rv*q.z;
    o.w = 0.4f*bs.w + bd*s.w + rv*q.w;
    out[idx] = o;
}

// ---------------- launch ----------------
extern "C" void kernel_launch(void* const* d_in, const int* in_sizes, int n_in,
                              void* d_out, int out_size) {
    const float* x    = (const float*)d_in[0];
    const void*  eraw = d_in[1];
    if (in_sizes[0] != Nn * Dd) { x = (const float*)d_in[1]; eraw = d_in[0]; }
    const int* ei32 = (const int*)eraw;
    float4*    yo   = (float4*)d_out;

    float *pAf;  cudaGetSymbolAddress((void**)&pAf, g_Af);
    uint2 *pAb;  cudaGetSymbolAddress((void**)&pAb, g_Ab);
    uint2 *pXb;  cudaGetSymbolAddress((void**)&pXb, g_Xb);
    uint2 *pbf0; cudaGetSymbolAddress((void**)&pbf0, g_bf0);
    uint2 *pbf1; cudaGetSymbolAddress((void**)&pbf1, g_bf1);

    // 1) zero bitmaps/barriers/q, u=1, dtype sniff
    k_init<<<1024, 256>>>(ei32);
    // 2) edge scatter into dedupe bitmaps (fwd + transpose)
    k_scatter2<<<NE / 256, 256>>>(ei32);
    // 3) CSR build (fwd+T) + X->bf16
    k_build_x2bf<<<3072, 256>>>((const float4*)x);
    // 4) fused: 4 power iters + q = 1.5 u^T X/(u^T v)
    k_upower<<<UPBLK, 1024>>>(x);
    // 5) R' = (I + 0.5*Ahat)X - v q^T   (fp32 + bf16)
    k_Rpass<<<Nn, 128>>>((const float4*)x, pXb, (float4*)pAf, pAb);
    // 6-7) two middle bulk passes (bf16)
    k_bulk<<<Nn, 128>>>(pAb,  pAb, pbf0);
    k_bulk<<<Nn, 128>>>(pbf0, pAb, pbf1);
    // 8) final
    k_final<<<Nn, 128>>>(pbf1, (const float4*)pAf, yo);
}